// round 4
// baseline (speedup 1.0000x reference)
#include <cuda_runtime.h>

// Problem constants (fixed shapes)
#define NWIN      2048     // 8 * 16 * 16 windows
#define NTHREADS  512

// SMEM layout (float offsets). Token tiles stored transposed: [ch*68 + n]
// (stride 68 floats = 16B-aligned rows, bank-balanced for strided float4).
#define OFF_X1   0          // 256*68 = 17408
#define OFF_TP   17408      // 17408
#define OFF_QH   34816      // 64*68 = 4352  (reused as O)
#define OFF_KH   39168
#define OFF_VH   43520
#define OFF_SS   47872
#define OFF_WB   52224
#define OFF_MV   56576      // 64 mask values
#define OFF_KP   56640      // keep flag
#define SMEM_FLOATS 56644
#define SMEM_BYTES (SMEM_FLOATS * 4)   // 226,576 B  (< 227 KB opt-in limit)

__device__ float g_scale[256];
__device__ float g_shift[256];

// (64 tok x 64 out) = (64 tok x 256 ch) @ (64 out x 256 ch)^T
// Xs: token tile transposed [ch*68 + n]; Wrow0: 64 consecutive weight rows,
// row stride 256; wb: staging (stride 68); Os: output [n*68 + d].
__device__ __forceinline__ void tok_gemm(const float* __restrict__ Xs,
                                         const float* __restrict__ Wrow0,
                                         float* __restrict__ wb,
                                         float* __restrict__ Os, int t)
{
    const int d = t & 63, g = t >> 6;
    float acc[8];
#pragma unroll
    for (int j = 0; j < 8; j++) acc[j] = 0.f;

    for (int kc = 0; kc < 4; kc++) {
        __syncthreads();                 // prior wb readers done
#pragma unroll
        for (int i = 0; i < 2; i++) {    // stage 64x64 weight chunk
            int li = t + i * NTHREADS;   // over 1024 float4
            int dr = li >> 4, c4 = li & 15;
            float4 v = *(const float4*)(Wrow0 + dr * 256 + kc * 64 + c4 * 4);
            *(float4*)(wb + dr * 68 + c4 * 4) = v;
        }
        __syncthreads();
#pragma unroll
        for (int c4 = 0; c4 < 16; c4++) {
            float4 wv = *(const float4*)(wb + d * 68 + c4 * 4);
            int ch = kc * 64 + c4 * 4;
#pragma unroll
            for (int u = 0; u < 4; u++) {
                float w = (u == 0) ? wv.x : (u == 1) ? wv.y : (u == 2) ? wv.z : wv.w;
                float4 xa = *(const float4*)(Xs + (ch + u) * 68 + g * 8);
                float4 xb = *(const float4*)(Xs + (ch + u) * 68 + g * 8 + 4);
                acc[0] += xa.x * w; acc[1] += xa.y * w;
                acc[2] += xa.z * w; acc[3] += xa.w * w;
                acc[4] += xb.x * w; acc[5] += xb.y * w;
                acc[6] += xb.z * w; acc[7] += xb.w * w;
            }
        }
    }
#pragma unroll
    for (int j = 0; j < 8; j++) Os[(g * 8 + j) * 68 + d] = acc[j];
}

__global__ void __launch_bounds__(NTHREADS, 1)
attn_kernel(const float* __restrict__ pre, const float* __restrict__ pmask,
            const float* __restrict__ feat, const float* __restrict__ fmask,
            const float* __restrict__ mask,
            const float* __restrict__ qw, const float* __restrict__ kvw,
            const float* __restrict__ pw, const float* __restrict__ pb,
            float* __restrict__ out)
{
    extern __shared__ float sm[];
    float* sx1 = sm + OFF_X1;
    float* stp = sm + OFF_TP;
    float* Qh  = sm + OFF_QH;   // per-head Q, later reused as attention output O
    float* Kh  = sm + OFF_KH;
    float* Vh  = sm + OFF_VH;
    float* Ss  = sm + OFF_SS;
    float* wb  = sm + OFF_WB;
    float* mv  = sm + OFF_MV;
    float* kp  = sm + OFF_KP;

    const int t  = threadIdx.x;
    const int wi = blockIdx.x;
    const int b  = wi >> 8;
    const int hb = (wi >> 4) & 15;
    const int wbk = wi & 15;
    const int h0 = hb * 8, w0 = wbk * 8;

    // ---- resized mask per token (half-pixel bilinear 64->128, edge clamp) ----
    if (t < 64) {
        int r = t >> 3, cp = t & 7;
        int hh = h0 + r, ww = w0 + cp;
        float sh = 0.5f * hh - 0.25f;
        float sw = 0.5f * ww - 0.25f;
        float fsh = floorf(sh), fsw = floorf(sw);
        int hi = (int)fsh, wx = (int)fsw;
        float fh = sh - fsh, fw = sw - fsw;
        int hA = min(max(hi, 0), 63),      hB = min(max(hi + 1, 0), 63);
        int wA = min(max(wx, 0), 63),      wB = min(max(wx + 1, 0), 63);
        const float* mb = mask + b * 4096;
        float v = (1.f - fh) * ((1.f - fw) * mb[hA * 64 + wA] + fw * mb[hA * 64 + wB])
                +        fh  * ((1.f - fw) * mb[hB * 64 + wA] + fw * mb[hB * 64 + wB]);
        v *= fmask[hh * 128 + ww];
        mv[t] = v;
    }
    __syncthreads();
    if (t == 0) {
        float mx = mv[0];
        for (int i = 1; i < 64; i++) mx = fmaxf(mx, mv[i]);
        kp[0] = (mx >= 0.2f) ? 1.f : 0.f;
    }

    // ---- load x1 = feat*fmask and temp = pre*pmask*mask tiles (transposed) ----
#pragma unroll 4
    for (int i = 0; i < 32; i++) {
        int li = t + i * NTHREADS;      // over 16384: [ch][n], n fastest
        int ch = li >> 6, n = li & 63;
        int r = n >> 3, cp = n & 7;
        int hh = h0 + r, ww = w0 + cp;
        int gidx = ((b * 256 + ch) * 128 + hh) * 128 + ww;
        float fm = fmask[hh * 128 + ww];
        float pm = pmask[hh * 128 + ww];
        sx1[ch * 68 + n] = feat[gidx] * fm;
        stp[ch * 68 + n] = pre[gidx] * pm * mv[n];
    }

    float facc[32];                      // final[n=g*8+j][c = (t&63)+64*kk]
#pragma unroll
    for (int i = 0; i < 32; i++) facc[i] = 0.f;

    const int d = t & 63, g = t >> 6;

    for (int h = 0; h < 4; h++) {
        tok_gemm(sx1, qw  +  h * 64        * 256, wb, Qh, t);
        tok_gemm(stp, kvw +  h * 64        * 256, wb, Kh, t);
        tok_gemm(stp, kvw + (256 + h * 64) * 256, wb, Vh, t);
        __syncthreads();

        // ---- scores S[n][m] = 0.125 * Q[n]·K[m]   (d plays role of m) ----
        {
            float acc[8];
#pragma unroll
            for (int j = 0; j < 8; j++) acc[j] = 0.f;
#pragma unroll
            for (int d4 = 0; d4 < 16; d4++) {
                float4 kv = *(const float4*)(Kh + d * 68 + d4 * 4);
#pragma unroll
                for (int j = 0; j < 8; j++) {
                    float4 q = *(const float4*)(Qh + (g * 8 + j) * 68 + d4 * 4);
                    acc[j] += q.x * kv.x + q.y * kv.y + q.z * kv.z + q.w * kv.w;
                }
            }
#pragma unroll
            for (int j = 0; j < 8; j++) Ss[(g * 8 + j) * 68 + d] = acc[j] * 0.125f;
        }
        __syncthreads();

        // ---- row softmax ----
        if (t < 64) {
            float mx = -1e30f;
            for (int m = 0; m < 64; m++) mx = fmaxf(mx, Ss[t * 68 + m]);
            float sum = 0.f;
            for (int m = 0; m < 64; m++) {
                float e = __expf(Ss[t * 68 + m] - mx);
                Ss[t * 68 + m] = e; sum += e;
            }
            float inv = 1.f / sum;
            for (int m = 0; m < 64; m++) Ss[t * 68 + m] *= inv;
        }
        __syncthreads();

        // ---- O[n][d] = sum_m P[n][m] * V[m][d]  (write O into Qh) ----
        {
            float acc[8];
#pragma unroll
            for (int j = 0; j < 8; j++) acc[j] = 0.f;
#pragma unroll
            for (int m4 = 0; m4 < 16; m4++) {
                float v0 = Vh[(m4 * 4 + 0) * 68 + d];
                float v1 = Vh[(m4 * 4 + 1) * 68 + d];
                float v2 = Vh[(m4 * 4 + 2) * 68 + d];
                float v3 = Vh[(m4 * 4 + 3) * 68 + d];
#pragma unroll
                for (int j = 0; j < 8; j++) {
                    float4 p = *(const float4*)(Ss + (g * 8 + j) * 68 + m4 * 4);
                    acc[j] += p.x * v0 + p.y * v1 + p.z * v2 + p.w * v3;
                }
            }
#pragma unroll
            for (int j = 0; j < 8; j++) Qh[(g * 8 + j) * 68 + d] = acc[j];
        }
        __syncthreads();

        // ---- proj accumulate: final[n][c] += O[n]·proj_w[c, h*64:+64] ----
        for (int kk = 0; kk < 4; kk++) {
            __syncthreads();
#pragma unroll
            for (int i = 0; i < 2; i++) {
                int li = t + i * NTHREADS;
                int cc = li >> 4, d4 = li & 15;
                *(float4*)(wb + cc * 68 + d4 * 4) =
                    *(const float4*)(pw + (kk * 64 + cc) * 256 + h * 64 + d4 * 4);
            }
            __syncthreads();
#pragma unroll
            for (int d4 = 0; d4 < 16; d4++) {
                float4 wv = *(const float4*)(wb + d * 68 + d4 * 4);
#pragma unroll
                for (int j = 0; j < 8; j++) {
                    float4 o = *(const float4*)(Qh + (g * 8 + j) * 68 + d4 * 4);
                    facc[j * 4 + kk] += o.x * wv.x + o.y * wv.y + o.z * wv.z + o.w * wv.w;
                }
            }
        }
    }

    __syncthreads();
    const float keepf = kp[0];
#pragma unroll
    for (int kk = 0; kk < 4; kk++) {
        int c = d + 64 * kk;
        float bias = pb[c];
#pragma unroll
        for (int j = 0; j < 8; j++) {
            int n = g * 8 + j;            // n = g*8+j  =>  row r = g, col = j
            float v = (facc[j * 4 + kk] + bias) * keepf + sx1[c * 68 + n];
            out[((b * 256 + c) * 128 + (h0 + g)) * 128 + (w0 + j)] = v;
        }
    }
}

// ---------------- BatchNorm (training-mode batch statistics) ----------------

__global__ void bn_stats_kernel(const float* __restrict__ x,
                                const float* __restrict__ gamma,
                                const float* __restrict__ beta)
{
    __shared__ float rs[256], rss[256];
    const int c = blockIdx.x, t = threadIdx.x;
    float s = 0.f, ss = 0.f;
    for (int bb = 0; bb < 8; bb++) {
        const float4* p = (const float4*)(x + (size_t)(bb * 256 + c) * 16384);
        for (int i = t; i < 4096; i += 256) {
            float4 v = p[i];
            s  += v.x + v.y + v.z + v.w;
            ss += v.x * v.x + v.y * v.y + v.z * v.z + v.w * v.w;
        }
    }
    rs[t] = s; rss[t] = ss;
    __syncthreads();
    for (int o = 128; o > 0; o >>= 1) {
        if (t < o) { rs[t] += rs[t + o]; rss[t] += rss[t + o]; }
        __syncthreads();
    }
    if (t == 0) {
        const float inv_n = 1.f / 131072.f;
        float mean = rs[0] * inv_n;
        float var  = rss[0] * inv_n - mean * mean;
        float rstd = rsqrtf(var + 1e-5f);
        float sc = gamma[c] * rstd;
        g_scale[c] = sc;
        g_shift[c] = beta[c] - mean * sc;
    }
}

__global__ void bn_apply_kernel(float* __restrict__ x)
{
    int i = blockIdx.x * blockDim.x + threadIdx.x;   // over 8,388,608 float4
    int c = (i >> 12) & 255;                          // 4096 float4 per (b,c)
    float sc = g_scale[c], sh = g_shift[c];
    float4* p = (float4*)x;
    float4 v = p[i];
    v.x = v.x * sc + sh; v.y = v.y * sc + sh;
    v.z = v.z * sc + sh; v.w = v.w * sc + sh;
    p[i] = v;
}

// ------------------------------- launch --------------------------------------

extern "C" void kernel_launch(void* const* d_in, const int* in_sizes, int n_in,
                              void* d_out, int out_size)
{
    const float* pre   = (const float*)d_in[0];
    const float* pmask = (const float*)d_in[1];
    const float* feat  = (const float*)d_in[2];
    const float* fmask = (const float*)d_in[3];
    const float* mask  = (const float*)d_in[4];
    const float* qw    = (const float*)d_in[5];
    const float* kvw   = (const float*)d_in[6];
    const float* pw    = (const float*)d_in[7];
    const float* pb    = (const float*)d_in[8];
    const float* gamma = (const float*)d_in[9];
    const float* beta  = (const float*)d_in[10];
    float* out = (float*)d_out;

    cudaFuncSetAttribute(attn_kernel,
                         cudaFuncAttributeMaxDynamicSharedMemorySize, SMEM_BYTES);

    attn_kernel<<<NWIN, NTHREADS, SMEM_BYTES>>>(pre, pmask, feat, fmask, mask,
                                                qw, kvw, pw, pb, out);
    bn_stats_kernel<<<256, 256>>>(out, gamma, beta);
    bn_apply_kernel<<<32768, 256>>>(out);
}

// round 6
// speedup vs baseline: 3.1571x; 3.1571x over previous
#include <cuda_runtime.h>
#include <cuda_bf16.h>
#include <mma.h>
#include <cstdint>

using namespace nvcuda;
typedef __nv_bfloat16 bf;

#define LDX  264   // x1/tp/wb weight stride (bf16 elems)
#define LDT  72    // small tile stride (bf16)
#define LDS_ 68    // f32 scratch stride
#define LDE  20    // f32 epilogue stage stride

// smem byte offsets
#define O_X1 0
#define O_TP 33792
#define O_WB 67584      // 64x264 weights OR 256x72 proj chunk (36864 B)
#define O_QH 104448
#define O_KH 113664
#define O_VH 122880
#define O_PH 132096
#define O_OH 141312
#define O_SS 150528     // 64x68 f32
#define O_ES 167936     // 16 warps x 16x20 f32
#define O_BS 188416     // 4x256 f32 bn sum
#define O_BQ 192512     // 4x256 f32 bn sumsq
#define O_MV 196608
#define O_FM 196864
#define O_PM 197120
#define O_KP 197376
#define SMEM_REQ 197408

__device__ bf qwb[256 * 256];
__device__ bf kvwb[512 * 256];
__device__ bf pwb[256 * 256];
__device__ float g_ps[256 * 2048];
__device__ float g_pq[256 * 2048];
__device__ float g_scale[256];
__device__ float g_shift[256];

__device__ __forceinline__ uint32_t pk2(float a, float b) {
    __nv_bfloat162 h = __floats2bfloat162_rn(a, b);
    return *(uint32_t*)&h;
}

// stage 64 weight rows (256 k each, bf16) into wb with stride LDX
__device__ __forceinline__ void stage_w(bf* wb, const bf* __restrict__ src, int t) {
    for (int i = t; i < 2048; i += 512) {
        int r = i >> 5, c8 = (i & 31) * 8;
        *(uint4*)&wb[r * LDX + c8] = *(const uint4*)&src[r * 256 + c8];
    }
}
// 64x64 f32 (ld 68) -> bf16 (ld 72), scaled
__device__ __forceinline__ void cvt64(bf* dst, const float* __restrict__ src, float sc, int t) {
    for (int i = t; i < 2048; i += 512) {
        int n = i >> 5, d2 = (i & 31) * 2;
        *(uint32_t*)&dst[n * LDT + d2] =
            pk2(src[n * LDS_ + d2] * sc, src[n * LDS_ + d2 + 1] * sc);
    }
}
// 64-tok x 64-out = A(64x256,ldx) @ W(64x256,ldx)^T ; warp does tile (mt,ng)
__device__ __forceinline__ void gemm256(const bf* A, const bf* W, float* S, int mt, int ng) {
    wmma::fragment<wmma::accumulator, 16, 16, 16, float> c;
    wmma::fill_fragment(c, 0.f);
#pragma unroll
    for (int k = 0; k < 16; k++) {
        wmma::fragment<wmma::matrix_a, 16, 16, 16, bf, wmma::row_major> a;
        wmma::fragment<wmma::matrix_b, 16, 16, 16, bf, wmma::col_major> b;
        wmma::load_matrix_sync(a, A + mt * 16 * LDX + k * 16, LDX);
        wmma::load_matrix_sync(b, W + ng * 16 * LDX + k * 16, LDX);
        wmma::mma_sync(c, a, b, c);
    }
    wmma::store_matrix_sync(S + mt * 16 * LDS_ + ng * 16, c, LDS_, wmma::mem_row_major);
}

__global__ void wconv(const float* __restrict__ qw, const float* __restrict__ kvw,
                      const float* __restrict__ pw) {
    int i = blockIdx.x * 256 + threadIdx.x;
    if (i < 65536)  qwb[i] = __float2bfloat16(qw[i]);
    if (i < 131072) kvwb[i] = __float2bfloat16(kvw[i]);
    if (i < 65536)  pwb[i] = __float2bfloat16(pw[i]);
}

__global__ void __launch_bounds__(512, 1)
attn(const float* __restrict__ pre, const float* __restrict__ pmask,
     const float* __restrict__ feat, const float* __restrict__ fmask,
     const float* __restrict__ mask, const float* __restrict__ pb,
     float* __restrict__ out)
{
    extern __shared__ char sm[];
    bf* x1 = (bf*)(sm + O_X1);
    bf* tp = (bf*)(sm + O_TP);
    bf* wb = (bf*)(sm + O_WB);
    bf* qh = (bf*)(sm + O_QH);
    bf* kh = (bf*)(sm + O_KH);
    bf* vh = (bf*)(sm + O_VH);
    bf* ph = (bf*)(sm + O_PH);
    bf* oh = (bf*)(sm + O_OH);
    float* ss  = (float*)(sm + O_SS);
    float* es  = (float*)(sm + O_ES);
    float* bnS = (float*)(sm + O_BS);
    float* bnQ = (float*)(sm + O_BQ);
    float* mv  = (float*)(sm + O_MV);
    float* fmv = (float*)(sm + O_FM);
    float* pmv = (float*)(sm + O_PM);
    float* kp  = (float*)(sm + O_KP);

    const int t = threadIdx.x, w = t >> 5, l = t & 31;
    const int mt = w & 3, ng = w >> 2;
    const int wi = blockIdx.x;
    const int b = wi >> 8;
    const int h0 = ((wi >> 4) & 15) * 8;
    const int w0 = (wi & 15) * 8;

    // bilinear mask 64->128 (half-pixel, clamp) + mask caches
    if (t < 64) {
        int r = t >> 3, cp = t & 7;
        int hh = h0 + r, ww = w0 + cp;
        float sh = 0.5f * hh - 0.25f, sw = 0.5f * ww - 0.25f;
        float fsh = floorf(sh), fsw = floorf(sw);
        int hi = (int)fsh, wx = (int)fsw;
        float fh = sh - fsh, fw = sw - fsw;
        int hA = min(max(hi, 0), 63), hB = min(max(hi + 1, 0), 63);
        int wA = min(max(wx, 0), 63), wB = min(max(wx + 1, 0), 63);
        const float* mb = mask + b * 4096;
        float fm = fmask[hh * 128 + ww];
        float v = (1.f - fh) * ((1.f - fw) * mb[hA * 64 + wA] + fw * mb[hA * 64 + wB])
                +        fh  * ((1.f - fw) * mb[hB * 64 + wA] + fw * mb[hB * 64 + wB]);
        mv[t]  = v * fm;
        fmv[t] = fm;
        pmv[t] = pmask[hh * 128 + ww];
    }
    __syncthreads();
    if (t == 0) {
        float mx = mv[0];
        for (int i = 1; i < 64; i++) mx = fmaxf(mx, mv[i]);
        kp[0] = (mx >= 0.2f) ? 1.f : 0.f;
    }

    // load x1 = feat*fm, tp = pre*pm*mv (bf16, [tok][ch])
#pragma unroll 4
    for (int it = 0; it < 32; it++) {
        int ch = (t >> 3) + (it & 3) * 64;
        int r = it >> 2, cp = t & 7, n = r * 8 + cp;
        size_t g = ((size_t)(b * 256 + ch) * 128 + h0 + r) * 128 + w0 + cp;
        x1[n * LDX + ch] = __float2bfloat16(feat[g] * fmv[n]);
        tp[n * LDX + ch] = __float2bfloat16(pre[g] * pmv[n] * mv[n]);
    }

    wmma::fragment<wmma::accumulator, 16, 16, 16, float> facc[4];
#pragma unroll
    for (int j = 0; j < 4; j++) wmma::fill_fragment(facc[j], 0.f);

    for (int h = 0; h < 4; h++) {
        // ---- Q projection (scaled 0.125 at convert) ----
        stage_w(wb, qwb + h * 64 * 256, t);
        __syncthreads();
        gemm256(x1, wb, ss, mt, ng);
        __syncthreads();
        cvt64(qh, ss, 0.125f, t);
        __syncthreads();
        // ---- K projection ----
        stage_w(wb, kvwb + h * 64 * 256, t);
        __syncthreads();
        gemm256(tp, wb, ss, mt, ng);
        __syncthreads();
        cvt64(kh, ss, 1.f, t);
        __syncthreads();
        // ---- V projection ----
        stage_w(wb, kvwb + (256 + h * 64) * 256, t);
        __syncthreads();
        gemm256(tp, wb, ss, mt, ng);
        __syncthreads();
        cvt64(vh, ss, 1.f, t);
        __syncthreads();

        // ---- S = Qs @ K^T (64x64x64) ----
        {
            wmma::fragment<wmma::accumulator, 16, 16, 16, float> c;
            wmma::fill_fragment(c, 0.f);
#pragma unroll
            for (int k = 0; k < 4; k++) {
                wmma::fragment<wmma::matrix_a, 16, 16, 16, bf, wmma::row_major> a;
                wmma::fragment<wmma::matrix_b, 16, 16, 16, bf, wmma::col_major> bb;
                wmma::load_matrix_sync(a, qh + mt * 16 * LDT + k * 16, LDT);
                wmma::load_matrix_sync(bb, kh + ng * 16 * LDT + k * 16, LDT);
                wmma::mma_sync(c, a, bb, c);
            }
            wmma::store_matrix_sync(ss + mt * 16 * LDS_ + ng * 16, c, LDS_, wmma::mem_row_major);
        }
        __syncthreads();

        // ---- row softmax: ss -> ph (bf16) ----
        if (t < 64) {
            float mx = -1e30f;
            for (int m = 0; m < 64; m++) mx = fmaxf(mx, ss[t * LDS_ + m]);
            float sum = 0.f;
            for (int m = 0; m < 64; m++) {
                float e = __expf(ss[t * LDS_ + m] - mx);
                ss[t * LDS_ + m] = e;
                sum += e;
            }
            float inv = 1.f / sum;
            for (int m = 0; m < 32; m++)
                *(uint32_t*)&ph[t * LDT + 2 * m] =
                    pk2(ss[t * LDS_ + 2 * m] * inv, ss[t * LDS_ + 2 * m + 1] * inv);
        }
        __syncthreads();

        // ---- O = P @ V (64x64x64) ----
        {
            wmma::fragment<wmma::accumulator, 16, 16, 16, float> c;
            wmma::fill_fragment(c, 0.f);
#pragma unroll
            for (int k = 0; k < 4; k++) {
                wmma::fragment<wmma::matrix_a, 16, 16, 16, bf, wmma::row_major> a;
                wmma::fragment<wmma::matrix_b, 16, 16, 16, bf, wmma::row_major> bb;
                wmma::load_matrix_sync(a, ph + mt * 16 * LDT + k * 16, LDT);
                wmma::load_matrix_sync(bb, vh + k * 16 * LDT + ng * 16, LDT);
                wmma::mma_sync(c, a, bb, c);
            }
            wmma::store_matrix_sync(ss + mt * 16 * LDS_ + ng * 16, c, LDS_, wmma::mem_row_major);
        }
        __syncthreads();
        cvt64(oh, ss, 1.f, t);
        __syncthreads();

        // ---- stage proj chunk: wb2[c][kd] = pw[c][h*64+kd], 256x64 ld LDT ----
        for (int i = t; i < 4096; i += 512) {
            int c = i >> 4, k4 = (i & 15) * 4;
            *(uint2*)&wb[c * LDT + k4] = *(const uint2*)&pwb[c * 256 + h * 64 + k4];
        }
        __syncthreads();

        // ---- proj accumulate: facc[j] += O @ pw_h^T ----
#pragma unroll
        for (int k = 0; k < 4; k++) {
            wmma::fragment<wmma::matrix_a, 16, 16, 16, bf, wmma::row_major> a;
            wmma::load_matrix_sync(a, oh + mt * 16 * LDT + k * 16, LDT);
#pragma unroll
            for (int j = 0; j < 4; j++) {
                int nt = ng * 4 + j;
                wmma::fragment<wmma::matrix_b, 16, 16, 16, bf, wmma::col_major> bb;
                wmma::load_matrix_sync(bb, wb + nt * 16 * LDT + k * 16, LDT);
                wmma::mma_sync(facc[j], a, bb, facc[j]);
            }
        }
        __syncthreads();
    }

    // ---- epilogue: out = (acc+bias)*keep + feat*fm ; fused BN partials ----
    const float keep = kp[0];
    float* eg = es + w * 16 * LDE;
#pragma unroll
    for (int j = 0; j < 4; j++) {
        wmma::store_matrix_sync(eg, facc[j], LDE, wmma::mem_row_major);
        __syncwarp();
        if (l < 16) {
            int c = ng * 64 + j * 16 + l;
            float bias = pb[c];
            float s = 0.f, q = 0.f;
#pragma unroll
            for (int m = 0; m < 16; m++) {
                int n = mt * 16 + m;
                int r = n >> 3, cp = n & 7;
                size_t g = ((size_t)(b * 256 + c) * 128 + h0 + r) * 128 + w0 + cp;
                float val = (eg[m * LDE + l] + bias) * keep + feat[g] * fmv[n];
                out[g] = val;
                s += val;
                q += val * val;
            }
            bnS[mt * 256 + c] = s;
            bnQ[mt * 256 + c] = q;
        }
        __syncwarp();
    }
    __syncthreads();
    if (t < 256) {
        float s = bnS[t] + bnS[256 + t] + bnS[512 + t] + bnS[768 + t];
        float q = bnQ[t] + bnQ[256 + t] + bnQ[512 + t] + bnQ[768 + t];
        g_ps[t * 2048 + wi] = s;
        g_pq[t * 2048 + wi] = q;
    }
}

// ---------------- BN finalize + apply ----------------
__global__ void bn_fin(const float* __restrict__ gamma, const float* __restrict__ beta) {
    __shared__ float rs[256], rq[256];
    const int c = blockIdx.x, t = threadIdx.x;
    float s = 0.f, q = 0.f;
    for (int i = t; i < 2048; i += 256) {
        s += g_ps[c * 2048 + i];
        q += g_pq[c * 2048 + i];
    }
    rs[t] = s; rq[t] = q;
    __syncthreads();
    for (int o = 128; o > 0; o >>= 1) {
        if (t < o) { rs[t] += rs[t + o]; rq[t] += rq[t + o]; }
        __syncthreads();
    }
    if (t == 0) {
        const float inv_n = 1.f / 131072.f;
        float mean = rs[0] * inv_n;
        float var  = rq[0] * inv_n - mean * mean;
        float sc = gamma[c] * rsqrtf(var + 1e-5f);
        g_scale[c] = sc;
        g_shift[c] = beta[c] - mean * sc;
    }
}

__global__ void bn_apply(float* __restrict__ x) {
    int i = blockIdx.x * blockDim.x + threadIdx.x;   // over 8,388,608 float4
    int c = (i >> 12) & 255;
    float sc = g_scale[c], sh = g_shift[c];
    float4* p = (float4*)x;
    float4 v = p[i];
    v.x = v.x * sc + sh; v.y = v.y * sc + sh;
    v.z = v.z * sc + sh; v.w = v.w * sc + sh;
    p[i] = v;
}

extern "C" void kernel_launch(void* const* d_in, const int* in_sizes, int n_in,
                              void* d_out, int out_size)
{
    const float* pre   = (const float*)d_in[0];
    const float* pmask = (const float*)d_in[1];
    const float* feat  = (const float*)d_in[2];
    const float* fmask = (const float*)d_in[3];
    const float* mask  = (const float*)d_in[4];
    const float* qw    = (const float*)d_in[5];
    const float* kvw   = (const float*)d_in[6];
    const float* pw    = (const float*)d_in[7];
    const float* pb    = (const float*)d_in[8];
    const float* gamma = (const float*)d_in[9];
    const float* beta  = (const float*)d_in[10];
    float* out = (float*)d_out;

    cudaFuncSetAttribute(attn, cudaFuncAttributeMaxDynamicSharedMemorySize, SMEM_REQ);

    wconv<<<512, 256>>>(qw, kvw, pw);
    attn<<<2048, 512, SMEM_REQ>>>(pre, pmask, feat, fmask, mask, pb, out);
    bn_fin<<<256, 256>>>(gamma, beta);
    bn_apply<<<8388608 / 256, 256>>>(out);
}

// round 7
// speedup vs baseline: 3.2087x; 1.0163x over previous
#include <cuda_runtime.h>
#include <cuda_bf16.h>
#include <mma.h>
#include <cstdint>

using namespace nvcuda;
typedef __nv_bfloat16 bf;

#define LDX 264      // x1/tp stride (bf16)
#define LDW 264      // weight stage stride
#define LDT 72       // small tile stride (bf16)
#define LDV 136      // V-weight half stride (bf16)
#define LDSP 68      // S f32 stride
#define LDE 20       // es f32 stride

// smem byte offsets
#define O_X1 0          // 128x264 bf16 = 67584
#define O_TP 67584
#define O_R3 135168     // 36864: Qw/Kw (64x264) | S f32 (128x68) | V tile (128x72) | projW (256x72)
#define O_R4 172032     // 18432: Qh | Vw halves (64x136) | Oh | BN partials
#define O_R5 190464     // 18432: Kh | P
#define O_ES 208896     // 16 warps x 16x20 f32 = 20480
#define O_MV 229376     // float[128]
#define O_FM 229888
#define O_PM 230400
#define O_KP 230912     // float[2]
#define SMEM_REQ 230928

__device__ bf qwb[256 * 256];
__device__ bf kvwb[512 * 256];
__device__ bf pwb[256 * 256];
__device__ float g_ps[256 * 1024];
__device__ float g_pq[256 * 1024];
__device__ float g_scale[256];
__device__ float g_shift[256];

__device__ __forceinline__ uint32_t pk2(float a, float b) {
    __nv_bfloat162 h = __floats2bfloat162_rn(a, b);
    return *(uint32_t*)&h;
}

typedef wmma::fragment<wmma::accumulator, 16, 16, 16, float> AccF;
typedef wmma::fragment<wmma::matrix_a, 16, 16, 16, bf, wmma::row_major> AFrag;
typedef wmma::fragment<wmma::matrix_b, 16, 16, 16, bf, wmma::col_major> BCol;
typedef wmma::fragment<wmma::matrix_b, 16, 16, 16, bf, wmma::row_major> BRow;

// store acc tile to warp scratch, convert to bf16 dst (stride LDT), scaled
__device__ __forceinline__ void cvt_tile(float* eg, bf* dst, int r0, int c0,
                                         float sc, int l, const AccF& c) {
    wmma::store_matrix_sync(eg, c, LDE, wmma::mem_row_major);
    __syncwarp();
    int rr = l >> 1, cc = (l & 1) * 8;
    const float* s = eg + rr * LDE + cc;
    uint32_t* d = (uint32_t*)(dst + (r0 + rr) * LDT + c0 + cc);
    d[0] = pk2(s[0] * sc, s[1] * sc);
    d[1] = pk2(s[2] * sc, s[3] * sc);
    d[2] = pk2(s[4] * sc, s[5] * sc);
    d[3] = pk2(s[6] * sc, s[7] * sc);
    __syncwarp();
}

__global__ void wconv(const float* __restrict__ qw, const float* __restrict__ kvw,
                      const float* __restrict__ pw) {
    int i = blockIdx.x * 256 + threadIdx.x;
    if (i < 65536)  qwb[i] = __float2bfloat16(qw[i]);
    if (i < 131072) kvwb[i] = __float2bfloat16(kvw[i]);
    if (i < 65536)  pwb[i] = __float2bfloat16(pw[i]);
}

__global__ void __launch_bounds__(512, 1)
attn(const float* __restrict__ pre, const float* __restrict__ pmask,
     const float* __restrict__ feat, const float* __restrict__ fmask,
     const float* __restrict__ mask, const float* __restrict__ pb,
     float* __restrict__ out)
{
    extern __shared__ char sm[];
    bf* x1 = (bf*)(sm + O_X1);
    bf* tp = (bf*)(sm + O_TP);
    bf* r3b = (bf*)(sm + O_R3);     // weight stage / V tile / proj chunk
    float* sp = (float*)(sm + O_R3); // S f32 view
    bf* r4b = (bf*)(sm + O_R4);     // Qh / Vw halves / Oh
    float* bnS = (float*)(sm + O_R4);
    float* bnQ = (float*)(sm + O_R4 + 8192);
    bf* r5b = (bf*)(sm + O_R5);     // Kh / P
    float* es  = (float*)(sm + O_ES);
    float* mv  = (float*)(sm + O_MV);
    float* fmv = (float*)(sm + O_FM);
    float* pmv = (float*)(sm + O_PM);
    float* kp  = (float*)(sm + O_KP);

    const int t = threadIdx.x, w = t >> 5, l = t & 31;
    const int mt = w & 7, ngp = (w >> 3) * 2;    // row tile, col-tile pair base
    float* eg = es + w * (16 * LDE);
    const int wi0 = blockIdx.x * 2;              // even window index
    const int b = wi0 >> 8;
    const int h0 = ((wi0 >> 4) & 15) * 8;
    const int w0p = (wi0 & 15) * 8;              // spans 16 cols (2 windows)

    // ---- mask bilinear (64->128 half-pixel clamp) for 128 tokens ----
    if (t < 128) {
        int q = t >> 6, loc = t & 63, r = loc >> 3, c = loc & 7;
        int hh = h0 + r, ww = w0p + q * 8 + c;
        float sh = 0.5f * hh - 0.25f, sw = 0.5f * ww - 0.25f;
        float fsh = floorf(sh), fsw = floorf(sw);
        int hi = (int)fsh, wx = (int)fsw;
        float fh = sh - fsh, fw = sw - fsw;
        int hA = min(max(hi, 0), 63), hB = min(max(hi + 1, 0), 63);
        int wA = min(max(wx, 0), 63), wB = min(max(wx + 1, 0), 63);
        const float* mb = mask + b * 4096;
        float fm = fmask[hh * 128 + ww];
        float v = (1.f - fh) * ((1.f - fw) * mb[hA * 64 + wA] + fw * mb[hA * 64 + wB])
                +        fh  * ((1.f - fw) * mb[hB * 64 + wA] + fw * mb[hB * 64 + wB]);
        mv[t] = v * fm;
        fmv[t] = fm;
        pmv[t] = pmask[hh * 128 + ww];
    }
    __syncthreads();
    if (t < 2) {
        float mx = mv[t * 64];
        for (int i = 1; i < 64; i++) mx = fmaxf(mx, mv[t * 64 + i]);
        kp[t] = (mx >= 0.2f) ? 1.f : 0.f;
    }

    // ---- load x1 = feat*fm, tp = pre*pm*mv (bf16 [tok][ch]) ----
    for (int i = t; i < 8192; i += 512) {
        int ch = i >> 5, rr = (i >> 2) & 7, c4 = i & 3;
        size_t g = ((size_t)(b * 256 + ch) * 128 + h0 + rr) * 128 + w0p + c4 * 4;
        float4 f = *(const float4*)(feat + g);
        float4 p = *(const float4*)(pre + g);
        float fe[4] = {f.x, f.y, f.z, f.w};
        float pe[4] = {p.x, p.y, p.z, p.w};
#pragma unroll
        for (int e = 0; e < 4; e++) {
            int col = c4 * 4 + e, q = col >> 3, c = col & 7;
            int n = q * 64 + rr * 8 + c;
            x1[n * LDX + ch] = __float2bfloat16(fe[e] * fmv[n]);
            tp[n * LDX + ch] = __float2bfloat16(pe[e] * pmv[n] * mv[n]);
        }
    }

    AccF facc[8];
#pragma unroll
    for (int j = 0; j < 8; j++) wmma::fill_fragment(facc[j], 0.f);

    for (int h = 0; h < 4; h++) {
        // ======== A: Q projection (K=256) -> Qh (R4), scale 0.125 ========
        {
            const bf* src = qwb + h * 64 * 256;
            for (int i = t; i < 2048; i += 512) {
                int dr = i >> 5, c8 = (i & 31) * 8;
                *(uint4*)&r3b[dr * LDW + c8] = *(const uint4*)&src[dr * 256 + c8];
            }
            __syncthreads();
            AccF c0, c1;
            wmma::fill_fragment(c0, 0.f); wmma::fill_fragment(c1, 0.f);
#pragma unroll
            for (int k = 0; k < 16; k++) {
                AFrag a; BCol b0, b1;
                wmma::load_matrix_sync(a, x1 + mt * 16 * LDX + k * 16, LDX);
                wmma::load_matrix_sync(b0, r3b + (ngp * 16) * LDW + k * 16, LDW);
                wmma::load_matrix_sync(b1, r3b + ((ngp + 1) * 16) * LDW + k * 16, LDW);
                wmma::mma_sync(c0, a, b0, c0);
                wmma::mma_sync(c1, a, b1, c1);
            }
            cvt_tile(eg, r4b, mt * 16, ngp * 16, 0.125f, l, c0);
            cvt_tile(eg, r4b, mt * 16, (ngp + 1) * 16, 0.125f, l, c1);
            __syncthreads();
        }
        // ======== B: K projection -> Kh (R5) ========
        {
            const bf* src = kvwb + h * 64 * 256;
            for (int i = t; i < 2048; i += 512) {
                int dr = i >> 5, c8 = (i & 31) * 8;
                *(uint4*)&r3b[dr * LDW + c8] = *(const uint4*)&src[dr * 256 + c8];
            }
            __syncthreads();
            AccF c0, c1;
            wmma::fill_fragment(c0, 0.f); wmma::fill_fragment(c1, 0.f);
#pragma unroll
            for (int k = 0; k < 16; k++) {
                AFrag a; BCol b0, b1;
                wmma::load_matrix_sync(a, tp + mt * 16 * LDX + k * 16, LDX);
                wmma::load_matrix_sync(b0, r3b + (ngp * 16) * LDW + k * 16, LDW);
                wmma::load_matrix_sync(b1, r3b + ((ngp + 1) * 16) * LDW + k * 16, LDW);
                wmma::mma_sync(c0, a, b0, c0);
                wmma::mma_sync(c1, a, b1, c1);
            }
            cvt_tile(eg, r5b, mt * 16, ngp * 16, 1.f, l, c0);
            cvt_tile(eg, r5b, mt * 16, (ngp + 1) * 16, 1.f, l, c1);
            __syncthreads();
        }
        // ======== D: S = Qh @ Kh^T (block-diag by window) -> sp f32 (R3) ========
        {
            const int q = mt >> 2;   // window of this row tile
#pragma unroll
            for (int jj = 0; jj < 2; jj++) {
                int ng = ngp + jj;
                AccF c;
                wmma::fill_fragment(c, 0.f);
#pragma unroll
                for (int k = 0; k < 4; k++) {
                    AFrag a; BCol bb;
                    wmma::load_matrix_sync(a, r4b + mt * 16 * LDT + k * 16, LDT);
                    wmma::load_matrix_sync(bb, r5b + (q * 64 + ng * 16) * LDT + k * 16, LDT);
                    wmma::mma_sync(c, a, bb, c);
                }
                wmma::store_matrix_sync(sp + mt * 16 * LDSP + ng * 16, c, LDSP,
                                        wmma::mem_row_major);
            }
            __syncthreads();
        }
        // ======== E: softmax sp -> P bf16 (R5), 4 threads/row ========
        {
            int row = t >> 2, part = t & 3;
            const float* sr = sp + row * LDSP + part * 16;
            float v[16], mx = -1e30f;
#pragma unroll
            for (int i = 0; i < 16; i++) { v[i] = sr[i]; mx = fmaxf(mx, v[i]); }
            mx = fmaxf(mx, __shfl_xor_sync(0xffffffffu, mx, 1));
            mx = fmaxf(mx, __shfl_xor_sync(0xffffffffu, mx, 2));
            float sum = 0.f;
#pragma unroll
            for (int i = 0; i < 16; i++) { v[i] = __expf(v[i] - mx); sum += v[i]; }
            sum += __shfl_xor_sync(0xffffffffu, sum, 1);
            sum += __shfl_xor_sync(0xffffffffu, sum, 2);
            float inv = 1.f / sum;
            uint32_t* d = (uint32_t*)(r5b + row * LDT + part * 16);
#pragma unroll
            for (int i = 0; i < 8; i++)
                d[i] = pk2(v[2 * i] * inv, v[2 * i + 1] * inv);
            __syncthreads();
        }
        // ======== C: V projection (K-split halves, Vw in R4) -> V tile (R3) ========
        {
            AccF c0, c1;
            wmma::fill_fragment(c0, 0.f); wmma::fill_fragment(c1, 0.f);
#pragma unroll
            for (int half = 0; half < 2; half++) {
                const bf* src = kvwb + (256 + h * 64) * 256 + half * 128;
                for (int i = t; i < 1024; i += 512) {
                    int dr = i >> 4, k8 = (i & 15) * 8;
                    *(uint4*)&r4b[dr * LDV + k8] = *(const uint4*)&src[dr * 256 + k8];
                }
                __syncthreads();
#pragma unroll
                for (int k = 0; k < 8; k++) {
                    AFrag a; BCol b0, b1;
                    wmma::load_matrix_sync(a, tp + mt * 16 * LDX + half * 128 + k * 16, LDX);
                    wmma::load_matrix_sync(b0, r4b + (ngp * 16) * LDV + k * 16, LDV);
                    wmma::load_matrix_sync(b1, r4b + ((ngp + 1) * 16) * LDV + k * 16, LDV);
                    wmma::mma_sync(c0, a, b0, c0);
                    wmma::mma_sync(c1, a, b1, c1);
                }
                __syncthreads();
            }
            cvt_tile(eg, r3b, mt * 16, ngp * 16, 1.f, l, c0);
            cvt_tile(eg, r3b, mt * 16, (ngp + 1) * 16, 1.f, l, c1);
            __syncthreads();
        }
        // ======== F: O = P @ V (block-diag) -> Oh (R4) ========
        {
            const int q = mt >> 2;
#pragma unroll
            for (int jj = 0; jj < 2; jj++) {
                int ng = ngp + jj;
                AccF c;
                wmma::fill_fragment(c, 0.f);
#pragma unroll
                for (int k = 0; k < 4; k++) {
                    AFrag a; BRow bb;
                    wmma::load_matrix_sync(a, r5b + mt * 16 * LDT + k * 16, LDT);
                    wmma::load_matrix_sync(bb, r3b + (q * 64 + k * 16) * LDT + ng * 16, LDT);
                    wmma::mma_sync(c, a, bb, c);
                }
                cvt_tile(eg, r4b, mt * 16, ng * 16, 1.f, l, c);
            }
            __syncthreads();
        }
        // ======== G: proj chunk stage (R3) + accumulate facc ========
        {
            for (int i = t; i < 4096; i += 512) {
                int c = i >> 4, k4 = (i & 15) * 4;
                *(uint2*)&r3b[c * LDT + k4] = *(const uint2*)&pwb[c * 256 + h * 64 + k4];
            }
            __syncthreads();
            const int cbase = (w >> 3) * 128;
#pragma unroll
            for (int k = 0; k < 4; k++) {
                AFrag a;
                wmma::load_matrix_sync(a, r4b + mt * 16 * LDT + k * 16, LDT);
#pragma unroll
                for (int j = 0; j < 8; j++) {
                    BCol bb;
                    wmma::load_matrix_sync(bb, r3b + (cbase + j * 16) * LDT + k * 16, LDT);
                    wmma::mma_sync(facc[j], a, bb, facc[j]);
                }
            }
            __syncthreads();
        }
    }

    // ---- epilogue: out = (acc+bias)*keep + feat*fm ; BN partials ----
    const int cbase = (w >> 3) * 128;
#pragma unroll
    for (int j = 0; j < 8; j++) {
        wmma::store_matrix_sync(eg, facc[j], LDE, wmma::mem_row_major);
        __syncwarp();
        if (l < 16) {
            int c = cbase + j * 16 + l;
            float bias = pb[c];
            float s = 0.f, qq = 0.f;
#pragma unroll
            for (int m = 0; m < 16; m++) {
                int n = mt * 16 + m;
                int q = n >> 6, loc = n & 63, r = loc >> 3, cp = loc & 7;
                size_t g = ((size_t)(b * 256 + c) * 128 + h0 + r) * 128 + w0p + q * 8 + cp;
                float val = (eg[m * LDE + l] + bias) * kp[q] + feat[g] * fmv[n];
                out[g] = val;
                s += val;
                qq += val * val;
            }
            bnS[mt * 256 + c] = s;
            bnQ[mt * 256 + c] = qq;
        }
        __syncwarp();
    }
    __syncthreads();
    if (t < 256) {
        float s = 0.f, q = 0.f;
#pragma unroll
        for (int m = 0; m < 8; m++) { s += bnS[m * 256 + t]; q += bnQ[m * 256 + t]; }
        g_ps[t * 1024 + blockIdx.x] = s;
        g_pq[t * 1024 + blockIdx.x] = q;
    }
}

// ---------------- BN finalize + apply ----------------
__global__ void bn_fin(const float* __restrict__ gamma, const float* __restrict__ beta) {
    __shared__ float rs[256], rq[256];
    const int c = blockIdx.x, t = threadIdx.x;
    float s = 0.f, q = 0.f;
    for (int i = t; i < 1024; i += 256) {
        s += g_ps[c * 1024 + i];
        q += g_pq[c * 1024 + i];
    }
    rs[t] = s; rq[t] = q;
    __syncthreads();
    for (int o = 128; o > 0; o >>= 1) {
        if (t < o) { rs[t] += rs[t + o]; rq[t] += rq[t + o]; }
        __syncthreads();
    }
    if (t == 0) {
        const float inv_n = 1.f / 131072.f;
        float mean = rs[0] * inv_n;
        float var  = rq[0] * inv_n - mean * mean;
        float sc = gamma[c] * rsqrtf(var + 1e-5f);
        g_scale[c] = sc;
        g_shift[c] = beta[c] - mean * sc;
    }
}

__global__ void bn_apply(float* __restrict__ x) {
    int i = blockIdx.x * blockDim.x + threadIdx.x;
    int c = (i >> 12) & 255;
    float sc = g_scale[c], sh = g_shift[c];
    float4* p = (float4*)x;
    float4 v = p[i];
    v.x = v.x * sc + sh; v.y = v.y * sc + sh;
    v.z = v.z * sc + sh; v.w = v.w * sc + sh;
    p[i] = v;
}

extern "C" void kernel_launch(void* const* d_in, const int* in_sizes, int n_in,
                              void* d_out, int out_size)
{
    const float* pre   = (const float*)d_in[0];
    const float* pmask = (const float*)d_in[1];
    const float* feat  = (const float*)d_in[2];
    const float* fmask = (const float*)d_in[3];
    const float* mask  = (const float*)d_in[4];
    const float* qw    = (const float*)d_in[5];
    const float* kvw   = (const float*)d_in[6];
    const float* pw    = (const float*)d_in[7];
    const float* pb    = (const float*)d_in[8];
    const float* gamma = (const float*)d_in[9];
    const float* beta  = (const float*)d_in[10];
    float* out = (float*)d_out;

    cudaFuncSetAttribute(attn, cudaFuncAttributeMaxDynamicSharedMemorySize, SMEM_REQ);

    wconv<<<512, 256>>>(qw, kvw, pw);
    attn<<<1024, 512, SMEM_REQ>>>(pre, pmask, feat, fmask, mask, pb, out);
    bn_fin<<<256, 256>>>(gamma, beta);
    bn_apply<<<8388608 / 256, 256>>>(out);
}

// round 10
// speedup vs baseline: 4.6080x; 1.4361x over previous
#include <cuda_runtime.h>
#include <cuda_bf16.h>
#include <mma.h>
#include <cstdint>

using namespace nvcuda;
typedef __nv_bfloat16 bf;

typedef wmma::fragment<wmma::accumulator, 16, 16, 16, float> AccF;
typedef wmma::fragment<wmma::matrix_a, 16, 16, 16, bf, wmma::row_major> AFrag;
typedef wmma::fragment<wmma::matrix_b, 16, 16, 16, bf, wmma::col_major> BCol;
typedef wmma::fragment<wmma::matrix_b, 16, 16, 16, bf, wmma::row_major> BRow;

// ---- device scratch (static allocation is the sanctioned path) ----
__device__ bf qwb[65536];            // q weights, pre-scaled by 0.125
__device__ bf kvwb[131072];
__device__ bf pwb[65536];
__device__ bf g_x1[33554432];        // [tok 131072][ch 256]
__device__ bf g_tp[33554432];
__device__ bf g_qkv[100663296];      // [tok][768]: Q|K|V
__device__ bf g_o[33554432];         // attention output
__device__ float g_keep[2048];
__device__ float g_ps[262144];       // [c 256][mblk 1024]
__device__ float g_pq[262144];
__device__ float g_scale[256];
__device__ float g_shift[256];

__device__ __forceinline__ uint32_t pk2(float a, float b) {
    __nv_bfloat162 h = __floats2bfloat162_rn(a, b);
    return *(uint32_t*)&h;
}

// ================= weight convert (Q scale folded) =================
__global__ void wconv(const float* __restrict__ qw, const float* __restrict__ kvw,
                      const float* __restrict__ pw) {
    int i = blockIdx.x * 256 + threadIdx.x;
    if (i < 65536)  qwb[i]  = __float2bfloat16(qw[i] * 0.125f);
    if (i < 131072) kvwb[i] = __float2bfloat16(kvw[i]);
    if (i < 65536)  pwb[i]  = __float2bfloat16(pw[i]);
}

// ================= prep: masked inputs -> token-major bf16 =================
__global__ void __launch_bounds__(256)
prep(const float* __restrict__ pre, const float* __restrict__ pmask,
     const float* __restrict__ feat, const float* __restrict__ fmask,
     const float* __restrict__ mask)
{
    extern __shared__ char sm[];
    bf* x1s = (bf*)sm;                       // 64 x 264
    bf* tps = (bf*)(sm + 33792);
    float* mv  = (float*)(sm + 67584);
    float* fmv = (float*)(sm + 67840);
    float* pmv = (float*)(sm + 68096);

    const int t = threadIdx.x, wi = blockIdx.x;
    const int b = wi >> 8, h0 = ((wi >> 4) & 15) * 8, w0 = (wi & 15) * 8;

    if (t < 64) {   // bilinear 64->128 half-pixel clamp
        int r = t >> 3, cp = t & 7;
        int hh = h0 + r, ww = w0 + cp;
        float sh = 0.5f * hh - 0.25f, sw = 0.5f * ww - 0.25f;
        float fsh = floorf(sh), fsw = floorf(sw);
        int hi = (int)fsh, wx = (int)fsw;
        float fh = sh - fsh, fw = sw - fsw;
        int hA = min(max(hi, 0), 63), hB = min(max(hi + 1, 0), 63);
        int wA = min(max(wx, 0), 63), wB = min(max(wx + 1, 0), 63);
        const float* mb = mask + b * 4096;
        float fm = fmask[hh * 128 + ww];
        float v = (1.f - fh) * ((1.f - fw) * mb[hA * 64 + wA] + fw * mb[hA * 64 + wB])
                +        fh  * ((1.f - fw) * mb[hB * 64 + wA] + fw * mb[hB * 64 + wB]);
        mv[t] = v * fm;
        fmv[t] = fm;
        pmv[t] = pmask[hh * 128 + ww];
    }
    __syncthreads();
    if (t == 0) {
        float mx = mv[0];
        for (int i = 1; i < 64; i++) mx = fmaxf(mx, mv[i]);
        g_keep[wi] = (mx >= 0.2f) ? 1.f : 0.f;
    }

    // stage x1 = feat*fm, tp = pre*pm*mv  (256 threads, 64 iters, full coverage)
#pragma unroll 4
    for (int it = 0; it < 64; it++) {
        int ch = (t >> 3) + (it & 7) * 32;   // 0..255
        int r = it >> 3;                      // 0..7
        int cp = t & 7, n = r * 8 + cp;
        size_t g = ((size_t)(b * 256 + ch) * 128 + h0 + r) * 128 + w0 + cp;
        x1s[n * 264 + ch] = __float2bfloat16(feat[g] * fmv[n]);
        tps[n * 264 + ch] = __float2bfloat16(pre[g] * pmv[n] * mv[n]);
    }
    __syncthreads();
#pragma unroll
    for (int it = 0; it < 8; it++) {
        int idx = it * 256 + t;
        int n = idx >> 5, u = idx & 31;
        size_t d = ((size_t)wi * 64 + n) * 256 + u * 8;
        *(uint4*)&g_x1[d] = *(const uint4*)&x1s[n * 264 + u * 8];
        *(uint4*)&g_tp[d] = *(const uint4*)&tps[n * 264 + u * 8];
    }
}

// ================= QKV GEMM: [131072 x 768] = A @ W^T =================
// grid (6, 1024): x=nblk, y=mblk. nblk<2: Q (A=g_x1); else K/V (A=g_tp).
#define GS 9216   // stage size in bf16 elems (128*72)
__global__ void __launch_bounds__(256)
qkv_gemm()
{
    extern __shared__ char sm[];
    bf* As = (bf*)sm;                 // [2][128*72]
    bf* Bs = (bf*)(sm + 36864);
    float* sp = (float*)sm;           // epilogue 128x132 f32

    const int t = threadIdx.x, w = t >> 5;
    const int nblk = blockIdx.x, mblk = blockIdx.y;
    const bf* Aab = (nblk < 2 ? g_x1 : g_tp) + (size_t)mblk * 128 * 256;
    const bf* Bb = (nblk == 0) ? qwb : (nblk == 1) ? qwb + 32768
                 : kvwb + (nblk - 2) * 32768;

    AccF acc[4][2];
#pragma unroll
    for (int i = 0; i < 4; i++)
#pragma unroll
        for (int j = 0; j < 2; j++) wmma::fill_fragment(acc[i][j], 0.f);

#define QKV_LOAD(s, kc) do { \
    _Pragma("unroll") \
    for (int i_ = 0; i_ < 4; i_++) { \
        int idx_ = t + i_ * 256, row_ = idx_ >> 3, c8_ = (idx_ & 7) * 8; \
        *(uint4*)&As[(s) * GS + row_ * 72 + c8_] = *(const uint4*)&Aab[(size_t)row_ * 256 + (kc) * 64 + c8_]; \
        *(uint4*)&Bs[(s) * GS + row_ * 72 + c8_] = *(const uint4*)&Bb[(size_t)row_ * 256 + (kc) * 64 + c8_]; \
    } } while (0)

    QKV_LOAD(0, 0);
    __syncthreads();
    const int m0 = (w >> 2) * 64, n0 = (w & 3) * 32;
    for (int kc = 0; kc < 4; kc++) {
        int s = kc & 1;
        if (kc < 3) QKV_LOAD(s ^ 1, kc + 1);
#pragma unroll
        for (int ks = 0; ks < 4; ks++) {
            AFrag a[4]; BCol b[2];
#pragma unroll
            for (int i = 0; i < 4; i++)
                wmma::load_matrix_sync(a[i], As + s * GS + (m0 + i * 16) * 72 + ks * 16, 72);
#pragma unroll
            for (int j = 0; j < 2; j++)
                wmma::load_matrix_sync(b[j], Bs + s * GS + (n0 + j * 16) * 72 + ks * 16, 72);
#pragma unroll
            for (int i = 0; i < 4; i++)
#pragma unroll
                for (int j = 0; j < 2; j++) wmma::mma_sync(acc[i][j], a[i], b[j], acc[i][j]);
        }
        __syncthreads();
    }
    // epilogue: f32 smem (row-major 128x132) -> bf16 g_qkv
#pragma unroll
    for (int i = 0; i < 4; i++)
#pragma unroll
        for (int j = 0; j < 2; j++)
            wmma::store_matrix_sync(sp + (m0 + i * 16) * 132 + n0 + j * 16, acc[i][j],
                                    132, wmma::mem_row_major);
    __syncthreads();
    size_t ob = (size_t)mblk * 128 * 768 + nblk * 128;
#pragma unroll
    for (int i = 0; i < 8; i++) {
        int idx = t + i * 256, row = idx >> 4, c8 = (idx & 15) * 8;
        const float* s8 = sp + row * 132 + c8;
        uint4 v;
        v.x = pk2(s8[0], s8[1]); v.y = pk2(s8[2], s8[3]);
        v.z = pk2(s8[4], s8[5]); v.w = pk2(s8[6], s8[7]);
        *(uint4*)&g_qkv[ob + (size_t)row * 768 + c8] = v;
    }
}

// ================= per-window attention =================
// 2048 CTAs x 256 thr; smem 54272 B; per head: S=QK^T, softmax, O=PV
__global__ void __launch_bounds__(256)
attn()
{
    extern __shared__ char sm[];
    float* sp = (float*)sm;           // 64 x 68 f32
    bf* qh = (bf*)(sm + 17408);       // 64 x 72
    bf* kh = (bf*)(sm + 26624);
    bf* vh = (bf*)(sm + 35840);
    bf* ph = (bf*)(sm + 45056);

    const int t = threadIdx.x, w = t >> 5;
    const size_t tau0 = (size_t)blockIdx.x * 64;
    const int mt = w & 3;

    for (int h = 0; h < 4; h++) {
        // load Q/K/V head tiles (64x64 bf16 each)
#pragma unroll
        for (int i = 0; i < 6; i++) {
            int idx = i * 256 + t;
            int tile = idx >> 9, rem = idx & 511;
            int r = rem >> 3, c8 = (rem & 7) * 8;
            uint4 v = *(const uint4*)&g_qkv[(tau0 + r) * 768 + tile * 256 + h * 64 + c8];
            bf* dst = (tile == 0) ? qh : (tile == 1) ? kh : vh;
            *(uint4*)&dst[r * 72 + c8] = v;
        }
        __syncthreads();
        // S = Q K^T  (Q pre-scaled)
#pragma unroll
        for (int jj = 0; jj < 2; jj++) {
            int ng = (w >> 2) * 2 + jj;
            AccF c;
            wmma::fill_fragment(c, 0.f);
#pragma unroll
            for (int k = 0; k < 4; k++) {
                AFrag a; BCol bb;
                wmma::load_matrix_sync(a, qh + mt * 16 * 72 + k * 16, 72);
                wmma::load_matrix_sync(bb, kh + ng * 16 * 72 + k * 16, 72);
                wmma::mma_sync(c, a, bb, c);
            }
            wmma::store_matrix_sync(sp + mt * 16 * 68 + ng * 16, c, 68, wmma::mem_row_major);
        }
        __syncthreads();
        // softmax, 4 threads per row
        {
            int row = t >> 2, part = t & 3;
            const float* sr = sp + row * 68 + part * 16;
            float v[16], mx = -1e30f;
#pragma unroll
            for (int i = 0; i < 16; i++) { v[i] = sr[i]; mx = fmaxf(mx, v[i]); }
            mx = fmaxf(mx, __shfl_xor_sync(0xffffffffu, mx, 1));
            mx = fmaxf(mx, __shfl_xor_sync(0xffffffffu, mx, 2));
            float sum = 0.f;
#pragma unroll
            for (int i = 0; i < 16; i++) { v[i] = __expf(v[i] - mx); sum += v[i]; }
            sum += __shfl_xor_sync(0xffffffffu, sum, 1);
            sum += __shfl_xor_sync(0xffffffffu, sum, 2);
            float inv = 1.f / sum;
            uint32_t* d = (uint32_t*)(ph + row * 72 + part * 16);
#pragma unroll
            for (int i = 0; i < 8; i++) d[i] = pk2(v[2 * i] * inv, v[2 * i + 1] * inv);
        }
        __syncthreads();
        // O = P V
#pragma unroll
        for (int jj = 0; jj < 2; jj++) {
            int ng = (w >> 2) * 2 + jj;
            AccF c;
            wmma::fill_fragment(c, 0.f);
#pragma unroll
            for (int k = 0; k < 4; k++) {
                AFrag a; BRow bb;
                wmma::load_matrix_sync(a, ph + mt * 16 * 72 + k * 16, 72);
                wmma::load_matrix_sync(bb, vh + k * 16 * 72 + ng * 16, 72);
                wmma::mma_sync(c, a, bb, c);
            }
            wmma::store_matrix_sync(sp + mt * 16 * 68 + ng * 16, c, 68, wmma::mem_row_major);
        }
        __syncthreads();
        // convert + write O head block
#pragma unroll
        for (int i = 0; i < 2; i++) {
            int idx = i * 256 + t;
            int r = idx >> 3, c8 = (idx & 7) * 8;
            const float* s8 = sp + r * 68 + c8;
            uint4 v;
            v.x = pk2(s8[0], s8[1]); v.y = pk2(s8[2], s8[3]);
            v.z = pk2(s8[4], s8[5]); v.w = pk2(s8[6], s8[7]);
            *(uint4*)&g_o[(tau0 + r) * 256 + h * 64 + c8] = v;
        }
        __syncthreads();
    }
}

// ================= proj GEMM + fused epilogue + BN partials =================
// grid (2, 1024): x=nblk (channel halves), y=mblk (128-token blocks)
// smem: max(As+Bs = 73728, sp 69632 + bnS 8192 + bnQ 8192 = 86016) -> 86016
__global__ void __launch_bounds__(256)
proj_gemm(const float* __restrict__ feat, const float* __restrict__ fmask,
          const float* __restrict__ pb, float* __restrict__ out)
{
    extern __shared__ char sm[];
    bf* As = (bf*)sm;
    bf* Bs = (bf*)(sm + 36864);
    float* sp = (float*)sm;                  // col-major 128c x 136 (69632 B)
    float* bnS = (float*)(sm + 69632);       // 128 x 16
    float* bnQ = (float*)(sm + 69632 + 8192);

    const int t = threadIdx.x, w = t >> 5;
    const int nblk = blockIdx.x, mblk = blockIdx.y;
    const bf* Aab = g_o + (size_t)mblk * 128 * 256;
    const bf* Bb = pwb + nblk * 32768;

    AccF acc[4][2];
#pragma unroll
    for (int i = 0; i < 4; i++)
#pragma unroll
        for (int j = 0; j < 2; j++) wmma::fill_fragment(acc[i][j], 0.f);

    QKV_LOAD(0, 0);
    __syncthreads();
    const int m0 = (w >> 2) * 64, n0 = (w & 3) * 32;
    for (int kc = 0; kc < 4; kc++) {
        int s = kc & 1;
        if (kc < 3) QKV_LOAD(s ^ 1, kc + 1);
#pragma unroll
        for (int ks = 0; ks < 4; ks++) {
            AFrag a[4]; BCol b[2];
#pragma unroll
            for (int i = 0; i < 4; i++)
                wmma::load_matrix_sync(a[i], As + s * GS + (m0 + i * 16) * 72 + ks * 16, 72);
#pragma unroll
            for (int j = 0; j < 2; j++)
                wmma::load_matrix_sync(b[j], Bs + s * GS + (n0 + j * 16) * 72 + ks * 16, 72);
#pragma unroll
            for (int i = 0; i < 4; i++)
#pragma unroll
                for (int j = 0; j < 2; j++) wmma::mma_sync(acc[i][j], a[i], b[j], acc[i][j]);
        }
        __syncthreads();
    }
    // stage accumulators col-major: sp[c * 136 + m]
#pragma unroll
    for (int i = 0; i < 4; i++)
#pragma unroll
        for (int j = 0; j < 2; j++)
            wmma::store_matrix_sync(sp + (n0 + j * 16) * 136 + m0 + i * 16, acc[i][j],
                                    136, wmma::mem_col_major);
    __syncthreads();

    const int wi0 = mblk * 2;
    const float keep0 = g_keep[wi0], keep1 = g_keep[wi0 + 1];
    const int c0 = nblk * 128;
#pragma unroll
    for (int iter = 0; iter < 8; iter++) {
        int idx = iter * 256 + t;
        int cl = idx >> 4, wr = idx & 15, win = wr >> 3, r = wr & 7;
        int c = c0 + cl;
        int wi = wi0 + win;
        int b = wi >> 8, h0 = ((wi >> 4) & 15) * 8, w0 = (wi & 15) * 8;
        int hh = h0 + r;
        size_t g = ((size_t)(b * 256 + c) * 128 + hh) * 128 + w0;
        float keep = win ? keep1 : keep0;
        float bias = pb[c];
        const float* srow = sp + cl * 136 + win * 64 + r * 8;
        const float* fm = fmask + hh * 128 + w0;
        float s = 0.f, q = 0.f, vv[8];
#pragma unroll
        for (int e = 0; e < 8; e++) {
            float val = (srow[e] + bias) * keep + feat[g + e] * fm[e];
            vv[e] = val; s += val; q += val * val;
        }
        float4 o0 = {vv[0], vv[1], vv[2], vv[3]};
        float4 o1 = {vv[4], vv[5], vv[6], vv[7]};
        *(float4*)&out[g] = o0;
        *(float4*)&out[g + 4] = o1;
        bnS[cl * 16 + wr] = s;
        bnQ[cl * 16 + wr] = q;
    }
    __syncthreads();
    if (t < 128) {
        float s = 0.f, q = 0.f;
#pragma unroll
        for (int m = 0; m < 16; m++) { s += bnS[t * 16 + m]; q += bnQ[t * 16 + m]; }
        g_ps[(size_t)(c0 + t) * 1024 + mblk] = s;
        g_pq[(size_t)(c0 + t) * 1024 + mblk] = q;
    }
}

// ================= BN finalize + apply =================
__global__ void bn_fin(const float* __restrict__ gamma, const float* __restrict__ beta) {
    __shared__ float rs[256], rq[256];
    const int c = blockIdx.x, t = threadIdx.x;
    float s = 0.f, q = 0.f;
    for (int i = t; i < 1024; i += 256) {
        s += g_ps[c * 1024 + i];
        q += g_pq[c * 1024 + i];
    }
    rs[t] = s; rq[t] = q;
    __syncthreads();
    for (int o = 128; o > 0; o >>= 1) {
        if (t < o) { rs[t] += rs[t + o]; rq[t] += rq[t + o]; }
        __syncthreads();
    }
    if (t == 0) {
        const float inv_n = 1.f / 131072.f;
        float mean = rs[0] * inv_n;
        float var = rq[0] * inv_n - mean * mean;
        float sc = gamma[c] * rsqrtf(var + 1e-5f);
        g_scale[c] = sc;
        g_shift[c] = beta[c] - mean * sc;
    }
}

__global__ void bn_apply(float* __restrict__ x) {
    int i = blockIdx.x * blockDim.x + threadIdx.x;
    int c = (i >> 12) & 255;
    float sc = g_scale[c], sh = g_shift[c];
    float4* p = (float4*)x;
    float4 v = p[i];
    v.x = v.x * sc + sh; v.y = v.y * sc + sh;
    v.z = v.z * sc + sh; v.w = v.w * sc + sh;
    p[i] = v;
}

// ================= launch =================
extern "C" void kernel_launch(void* const* d_in, const int* in_sizes, int n_in,
                              void* d_out, int out_size)
{
    const float* pre   = (const float*)d_in[0];
    const float* pmask = (const float*)d_in[1];
    const float* feat  = (const float*)d_in[2];
    const float* fmask = (const float*)d_in[3];
    const float* mask  = (const float*)d_in[4];
    const float* qw    = (const float*)d_in[5];
    const float* kvw   = (const float*)d_in[6];
    const float* pw    = (const float*)d_in[7];
    const float* pb    = (const float*)d_in[8];
    const float* gamma = (const float*)d_in[9];
    const float* beta  = (const float*)d_in[10];
    float* out = (float*)d_out;

    cudaFuncSetAttribute(prep, cudaFuncAttributeMaxDynamicSharedMemorySize, 68352);
    cudaFuncSetAttribute(qkv_gemm, cudaFuncAttributeMaxDynamicSharedMemorySize, 73728);
    cudaFuncSetAttribute(attn, cudaFuncAttributeMaxDynamicSharedMemorySize, 54272);
    cudaFuncSetAttribute(proj_gemm, cudaFuncAttributeMaxDynamicSharedMemorySize, 86016);

    wconv<<<512, 256>>>(qw, kvw, pw);
    prep<<<2048, 256, 68352>>>(pre, pmask, feat, fmask, mask);
    qkv_gemm<<<dim3(6, 1024), 256, 73728>>>();
    attn<<<2048, 256, 54272>>>();
    proj_gemm<<<dim3(2, 1024), 256, 86016>>>(feat, fmask, pb, out);
    bn_fin<<<256, 256>>>(gamma, beta);
    bn_apply<<<32768, 256>>>(out);
}